// round 15
// baseline (speedup 1.0000x reference)
#include <cuda_runtime.h>
#include <cstdint>
#include <cuda_fp16.h>
#include <mma.h>
using namespace nvcuda;

// Problem dims
constexpr int kB = 64;      // batch
constexpr int kT = 512;     // seq len
constexpr int kE = 512;     // embed
constexpr int kH = 1024;    // hidden
constexpr int kBT = kB * kT;           // 32768
constexpr int k3H = 3 * kH;            // 3072
constexpr size_t kXPSZ = (size_t)kBT * k3H;       // per-dir xp elements
constexpr size_t kOUTSZ = (size_t)kBT * 2 * kH;   // outputs elements

// Scratch
__device__ __half g_emb[(size_t)kBT * kE];  // 32 MB (fp16 embeddings)
__device__ __half g_xp[2 * kXPSZ];          // 403 MB, [dir][t][b][3H] fp16
__device__ __half g_h[2][2][kB * kH];       // [parity][dir][b][j] fp16
__device__ unsigned int g_bar[2];           // per-dir step barrier counters

// ---------------------------------------------------------------------------
__global__ void zero_h_kernel() {
    int idx = blockIdx.x * blockDim.x + threadIdx.x;  // 131072 uints = 512KB
    ((unsigned int*)g_h)[idx] = 0u;
    if (blockIdx.x == 0 && threadIdx.x < 2) g_bar[threadIdx.x] = 0u;
}

// emb[m, :] = half(embed_W[seqs[m], :])
__global__ void gather_kernel(const int* __restrict__ seqs,
                              const float* __restrict__ embW) {
    int m = blockIdx.x;
    int t = threadIdx.x;  // 128 threads, 4 elems each
    int row = seqs[m];
    float4 v = reinterpret_cast<const float4*>(embW)[(size_t)row * (kE / 4) + t];
    __half2 h0 = __floats2half2_rn(v.x, v.y);
    __half2 h1 = __floats2half2_rn(v.z, v.w);
    *reinterpret_cast<__half2*>(&g_emb[(size_t)m * kE + t * 4]) = h0;
    *reinterpret_cast<__half2*>(&g_emb[(size_t)m * kE + t * 4 + 2]) = h1;
}

// ---------------------------------------------------------------------------
// xp = emb @ W_ih^T + b_ih (fp16 in, fp32 accum, fp16 OUT), rows [t][b].
__global__ void xp_gemm_kernel(const float* __restrict__ Wf,
                               const float* __restrict__ Wb,
                               const float* __restrict__ bf,
                               const float* __restrict__ bb) {
    constexpr int BM = 128, BN = 64, BK = 32, BKP = 40;
    __shared__ __half As[BM][BKP];
    __shared__ __half Bs[BN][BKP];
    __shared__ float Cs[8][32][32];

    int dir = blockIdx.z;
    const float* W = dir ? Wb : Wf;
    const float* bias = dir ? bb : bf;
    __half* xp = g_xp + (size_t)dir * kXPSZ;

    int m0 = blockIdx.y * BM, n0 = blockIdx.x * BN;
    int tid = threadIdx.x, wid = tid >> 5, lane = tid & 31;
    int wm = wid >> 1, wn = wid & 1;

    wmma::fragment<wmma::accumulator, 16, 16, 16, float> acc[2][2];
#pragma unroll
    for (int i = 0; i < 2; i++)
#pragma unroll
        for (int j = 0; j < 2; j++) wmma::fill_fragment(acc[i][j], 0.0f);

    for (int k0 = 0; k0 < kE; k0 += BK) {
#pragma unroll
        for (int it = 0; it < 2; it++) {
            int i = tid + it * 256;
            int r = i >> 2, c8 = i & 3;
            uint4 v = *reinterpret_cast<const uint4*>(
                &g_emb[(size_t)(m0 + r) * kE + k0 + c8 * 8]);
            *reinterpret_cast<uint4*>(&As[r][c8 * 8]) = v;
        }
        {
            int r = tid >> 2, c8 = tid & 3;
            const float* src = &W[(size_t)(n0 + r) * kE + k0 + c8 * 8];
            float4 v0 = *reinterpret_cast<const float4*>(src);
            float4 v1 = *reinterpret_cast<const float4*>(src + 4);
            __half2* dst = reinterpret_cast<__half2*>(&Bs[r][c8 * 8]);
            dst[0] = __floats2half2_rn(v0.x, v0.y);
            dst[1] = __floats2half2_rn(v0.z, v0.w);
            dst[2] = __floats2half2_rn(v1.x, v1.y);
            dst[3] = __floats2half2_rn(v1.z, v1.w);
        }
        __syncthreads();
#pragma unroll
        for (int kk = 0; kk < BK; kk += 16) {
            wmma::fragment<wmma::matrix_a, 16, 16, 16, __half,
                           wmma::row_major> a[2];
            wmma::fragment<wmma::matrix_b, 16, 16, 16, __half,
                           wmma::col_major> b[2];
            wmma::load_matrix_sync(a[0], &As[wm * 32][kk], BKP);
            wmma::load_matrix_sync(a[1], &As[wm * 32 + 16][kk], BKP);
            wmma::load_matrix_sync(b[0], &Bs[wn * 32][kk], BKP);
            wmma::load_matrix_sync(b[1], &Bs[wn * 32 + 16][kk], BKP);
#pragma unroll
            for (int i = 0; i < 2; i++)
#pragma unroll
                for (int j = 0; j < 2; j++)
                    wmma::mma_sync(acc[i][j], a[i], b[j], acc[i][j]);
        }
        __syncthreads();
    }
#pragma unroll
    for (int i = 0; i < 2; i++)
#pragma unroll
        for (int j = 0; j < 2; j++)
            wmma::store_matrix_sync(&Cs[wid][i * 16][j * 16], acc[i][j], 32,
                                    wmma::mem_row_major);
    __syncwarp();
    int gm = m0 + wm * 32, gn = n0 + wn * 32;
    float bv = bias[gn + lane];
#pragma unroll
    for (int r = 0; r < 32; r++) {
        int m = gm + r;                       // m = b*T + t
        int trow = (m & (kT - 1)) * kB + (m >> 9);  // -> t*B + b
        xp[(size_t)trow * k3H + gn + lane] =
            __float2half_rn(Cs[wid][r][lane] + bv);
    }
}

// ---------------------------------------------------------------------------
// Persistent GRU recurrence (R10 structure: best known).
// 128 blocks (64/dir), 16 hidden cols each. 16 warps = 4 m-tiles x 4
// K-quarters; A fragments row-major m16n16k16 from global h; B from SMEM W.
constexpr int WS_ST = 1032;                   // halves: 1024 + 8 pad
constexpr int CS_ST = 52;
constexpr int SM_WS_H = 48 * WS_ST;           // 49536 halves = 99072 B
constexpr int SM_CBUF = kB * CS_ST;           // 3328 floats per buffer
constexpr size_t SM_BYTES =
    (size_t)SM_WS_H * 2 + (size_t)(2 * SM_CBUF + 64) * 4;  // ~126 KB
constexpr int NTHR = 512;                     // 16 warps

__global__ void __launch_bounds__(NTHR, 1)
step_persist_kernel(const float* __restrict__ Whf,
                    const float* __restrict__ Whb,
                    const float* __restrict__ bhf,
                    const float* __restrict__ bhb,
                    float* __restrict__ out) {
    extern __shared__ char smraw[];
    __half* Ws = reinterpret_cast<__half*>(smraw);      // [48][WS_ST] halves
    float* bufA = reinterpret_cast<float*>(smraw + SM_WS_H * 2);
    float* bufB = bufA + SM_CBUF;
    float* bsl = bufB + SM_CBUF;                        // [48]

    int bx = blockIdx.x;
    int dir = bx >> 6;
    int j0 = (bx & 63) * 16;
    const float* W = dir ? Whb : Whf;
    const float* bhh = dir ? bhb : bhf;
    const __half* xp = g_xp + (size_t)dir * kXPSZ;

    int tid = threadIdx.x, wid = tid >> 5;
    int ks = wid >> 2;     // K-quarter 0..3 (256 K each)
    int mt = wid & 3;      // m-tile 0..3

    // preload W slice (48 rows x 1024) into SMEM as fp16
    for (int i = tid; i < 48 * 256; i += NTHR) {
        int r = i >> 8, c4 = i & 255;  // 4 floats per chunk
        int wrow = (r >> 4) * kH + j0 + (r & 15);
        float4 v = *reinterpret_cast<const float4*>(
            &W[(size_t)wrow * kH + c4 * 4]);
        __half2* dst = reinterpret_cast<__half2*>(&Ws[r * WS_ST + c4 * 4]);
        dst[0] = __floats2half2_rn(v.x, v.y);
        dst[1] = __floats2half2_rn(v.z, v.w);
    }
    if (tid < 48) bsl[tid] = bhh[(tid >> 4) * kH + j0 + (tid & 15)];
    __syncthreads();

    for (int s = 0; s < kT; s++) {
        int parity = s & 1;
        const __half* hprev = g_h[parity][dir];   // [b][j] row-major
        __half* hnext = g_h[parity ^ 1][dir];
        int t_idx = dir ? (kT - 1 - s) : s;
        const __half* xpt = xp + (size_t)t_idx * kB * k3H;

        // preload epilogue operands (latency hides behind mainloop)
        float pxr[2], pxz[2], pxn[2], php[2];
#pragma unroll
        for (int k = 0; k < 2; k++) {
            int idx = tid + k * NTHR;  // < 1024 always
            int b = idx >> 4, jj = idx & 15, j = j0 + jj;
            const __half* xpr = xpt + (size_t)b * k3H;
            pxr[k] = __half2float(xpr[j]);
            pxz[k] = __half2float(xpr[kH + j]);
            pxn[k] = __half2float(xpr[2 * kH + j]);
            php[k] = __half2float(hprev[b * kH + j]);
        }

        // ---------------- mainloop: no block syncs, 2-deep A ring ---------
        wmma::fragment<wmma::accumulator, 16, 16, 16, float> acc[3];
#pragma unroll
        for (int g = 0; g < 3; g++) wmma::fill_fragment(acc[g], 0.0f);

        const __half* aBase = hprev + (size_t)(mt * 16) * kH + ks * 256;
        wmma::fragment<wmma::matrix_a, 16, 16, 16, __half, wmma::row_major>
            afr[2];
        wmma::load_matrix_sync(afr[0], aBase, kH);
#pragma unroll 4
        for (int f = 0; f < 16; f++) {   // 16 k16-fragments per K-quarter
            int cur = f & 1;
            if (f < 15)
                wmma::load_matrix_sync(afr[cur ^ 1], aBase + (f + 1) * 16, kH);
            int kcol = ks * 256 + f * 16;
#pragma unroll
            for (int g = 0; g < 3; g++) {
                wmma::fragment<wmma::matrix_b, 16, 16, 16, __half,
                               wmma::col_major> b;
                wmma::load_matrix_sync(b, &Ws[(g * 16) * WS_ST + kcol], WS_ST);
                wmma::mma_sync(acc[g], afr[cur], b, acc[g]);
            }
        }

        // ---------------- K-partial reduction (2 syncs) -------------------
        float* mybuf = (ks & 1) ? bufB : bufA;
        if (ks >= 2) {
#pragma unroll
            for (int g = 0; g < 3; g++)
                wmma::store_matrix_sync(&mybuf[(mt * 16) * CS_ST + g * 16],
                                        acc[g], CS_ST, wmma::mem_row_major);
        }
        __syncthreads();
        if (ks < 2) {
#pragma unroll
            for (int g = 0; g < 3; g++) {
                wmma::fragment<wmma::accumulator, 16, 16, 16, float> c;
                wmma::load_matrix_sync(c, &mybuf[(mt * 16) * CS_ST + g * 16],
                                       CS_ST, wmma::mem_row_major);
#pragma unroll
                for (int e = 0; e < c.num_elements; e++)
                    acc[g].x[e] += c.x[e];
                wmma::store_matrix_sync(&mybuf[(mt * 16) * CS_ST + g * 16],
                                        acc[g], CS_ST, wmma::mem_row_major);
            }
        }
        __syncthreads();

        // ---------------- gate fusion + h update ---------------------------
        float hv[2];
#pragma unroll
        for (int k = 0; k < 2; k++) {
            int idx = tid + k * NTHR;
            int b = idx >> 4, jj = idx & 15, j = j0 + jj;
            float ghr = bufA[b * CS_ST + jj] + bufB[b * CS_ST + jj] + bsl[jj];
            float ghz = bufA[b * CS_ST + 16 + jj] + bufB[b * CS_ST + 16 + jj] +
                        bsl[16 + jj];
            float ghn = bufA[b * CS_ST + 32 + jj] + bufB[b * CS_ST + 32 + jj] +
                        bsl[32 + jj];
            float r = 1.0f / (1.0f + __expf(-(pxr[k] + ghr)));
            float z = 1.0f / (1.0f + __expf(-(pxz[k] + ghz)));
            float n = tanhf(pxn[k] + r * ghn);
            hv[k] = (1.0f - z) * n + z * php[k];
            hnext[b * kH + j] = __float2half_rn(hv[k]);
        }

        // arrive early; out-stores overlap the inter-block wait
        __threadfence();
        __syncthreads();
        if (tid == 0) atomicAdd(&g_bar[dir], 1u);
#pragma unroll
        for (int k = 0; k < 2; k++) {
            int idx = tid + k * NTHR;
            int b = idx >> 4, jj = idx & 15, j = j0 + jj;
            out[(size_t)(b * kT + t_idx) * (2 * kH) + dir * kH + j] = hv[k];
        }
        if (tid == 0) {
            unsigned int target = 64u * (unsigned int)(s + 1);
            unsigned int v;
            do {
                asm volatile("ld.acquire.gpu.u32 %0, [%1];"
                             : "=r"(v) : "l"(&g_bar[dir]) : "memory");
            } while (v < target);
        }
        __syncthreads();
    }
}

// ---------------------------------------------------------------------------
__global__ void fc_kernel(const float* __restrict__ fcW,
                          const float* __restrict__ fcb,
                          float* __restrict__ out) {
    __shared__ float hc[2 * kH];
    int b = blockIdx.y;
    int tid = threadIdx.x, wid = tid >> 5, lane = tid & 31;
    for (int k = tid; k < 2 * kH; k += 256) {
        hc[k] = (k < kH) ? __half2float(g_h[0][0][b * kH + k])
                         : __half2float(g_h[0][1][b * kH + k - kH]);
    }
    __syncthreads();
    int o = blockIdx.x * 8 + wid;
    const float4* wr = reinterpret_cast<const float4*>(&fcW[(size_t)o * 2 * kH]);
    const float4* hr = reinterpret_cast<const float4*>(hc);
    float sum = 0.0f;
    for (int i = lane; i < (2 * kH) / 4; i += 32) {
        float4 w = wr[i], h = hr[i];
        sum += w.x * h.x + w.y * h.y + w.z * h.z + w.w * h.w;
    }
#pragma unroll
    for (int off = 16; off; off >>= 1)
        sum += __shfl_xor_sync(0xffffffff, sum, off);
    if (lane == 0) out[kOUTSZ + (size_t)b * kH + o] = tanhf(sum + fcb[o]);
}

// ---------------------------------------------------------------------------
extern "C" void kernel_launch(void* const* d_in, const int* in_sizes, int n_in,
                              void* d_out, int out_size) {
    const int* seqs      = (const int*)d_in[0];
    const float* embW    = (const float*)d_in[1];
    const float* W_ih_f  = (const float*)d_in[2];
    const float* W_hh_f  = (const float*)d_in[3];
    const float* b_ih_f  = (const float*)d_in[4];
    const float* b_hh_f  = (const float*)d_in[5];
    const float* W_ih_b  = (const float*)d_in[6];
    const float* W_hh_b  = (const float*)d_in[7];
    const float* b_ih_b  = (const float*)d_in[8];
    const float* b_hh_b  = (const float*)d_in[9];
    const float* fc_W    = (const float*)d_in[10];
    const float* fc_b    = (const float*)d_in[11];
    float* out = (float*)d_out;

    static bool attr_set = false;
    if (!attr_set) {
        cudaFuncSetAttribute(step_persist_kernel,
                             cudaFuncAttributeMaxDynamicSharedMemorySize,
                             (int)SM_BYTES);
        attr_set = true;
    }

    zero_h_kernel<<<512, 256>>>();
    gather_kernel<<<kBT, 128>>>(seqs, embW);
    xp_gemm_kernel<<<dim3(48, 256, 2), 256>>>(W_ih_f, W_ih_b, b_ih_f, b_ih_b);
    step_persist_kernel<<<128, NTHR, SM_BYTES>>>(W_hh_f, W_hh_b, b_hh_f,
                                                 b_hh_b, out);
    fc_kernel<<<dim3(kH / 8, kB), 256>>>(fc_W, fc_b, out);
}

// round 16
// speedup vs baseline: 1.4946x; 1.4946x over previous
#include <cuda_runtime.h>
#include <cstdint>
#include <cuda_fp16.h>
#include <mma.h>
using namespace nvcuda;

// Problem dims
constexpr int kB = 64;      // batch
constexpr int kT = 512;     // seq len
constexpr int kE = 512;     // embed
constexpr int kH = 1024;    // hidden
constexpr int kBT = kB * kT;           // 32768
constexpr int k3H = 3 * kH;            // 3072
constexpr size_t kXPSZ = (size_t)kBT * k3H;       // per-dir xp elements
constexpr size_t kOUTSZ = (size_t)kBT * 2 * kH;   // outputs elements

// Scratch
__device__ __half g_emb[(size_t)kBT * kE];  // 32 MB (fp16 embeddings)
__device__ __half g_xp[2 * kXPSZ];          // 403 MB, [dir][t][b][3H] fp16
__device__ __half g_h[2][2][kB * kH];       // [parity][dir][b][j] fp16
__device__ unsigned int g_bar[2];           // per-dir step barrier counters

// ---------------------------------------------------------------------------
__global__ void zero_h_kernel() {
    int idx = blockIdx.x * blockDim.x + threadIdx.x;  // 131072 uints = 512KB
    ((unsigned int*)g_h)[idx] = 0u;
    if (blockIdx.x == 0 && threadIdx.x < 2) g_bar[threadIdx.x] = 0u;
}

// emb[m, :] = half(embed_W[seqs[m], :])
__global__ void gather_kernel(const int* __restrict__ seqs,
                              const float* __restrict__ embW) {
    int m = blockIdx.x;
    int t = threadIdx.x;  // 128 threads, 4 elems each
    int row = seqs[m];
    float4 v = reinterpret_cast<const float4*>(embW)[(size_t)row * (kE / 4) + t];
    __half2 h0 = __floats2half2_rn(v.x, v.y);
    __half2 h1 = __floats2half2_rn(v.z, v.w);
    *reinterpret_cast<__half2*>(&g_emb[(size_t)m * kE + t * 4]) = h0;
    *reinterpret_cast<__half2*>(&g_emb[(size_t)m * kE + t * 4 + 2]) = h1;
}

// ---------------------------------------------------------------------------
// xp = emb @ W_ih^T + b_ih (fp16 in, fp32 accum, fp16 OUT), rows [t][b].
__global__ void xp_gemm_kernel(const float* __restrict__ Wf,
                               const float* __restrict__ Wb,
                               const float* __restrict__ bf,
                               const float* __restrict__ bb) {
    constexpr int BM = 128, BN = 64, BK = 32, BKP = 40;
    __shared__ __half As[BM][BKP];
    __shared__ __half Bs[BN][BKP];
    __shared__ float Cs[8][32][32];

    int dir = blockIdx.z;
    const float* W = dir ? Wb : Wf;
    const float* bias = dir ? bb : bf;
    __half* xp = g_xp + (size_t)dir * kXPSZ;

    int m0 = blockIdx.y * BM, n0 = blockIdx.x * BN;
    int tid = threadIdx.x, wid = tid >> 5, lane = tid & 31;
    int wm = wid >> 1, wn = wid & 1;

    wmma::fragment<wmma::accumulator, 16, 16, 16, float> acc[2][2];
#pragma unroll
    for (int i = 0; i < 2; i++)
#pragma unroll
        for (int j = 0; j < 2; j++) wmma::fill_fragment(acc[i][j], 0.0f);

    for (int k0 = 0; k0 < kE; k0 += BK) {
#pragma unroll
        for (int it = 0; it < 2; it++) {
            int i = tid + it * 256;
            int r = i >> 2, c8 = i & 3;
            uint4 v = *reinterpret_cast<const uint4*>(
                &g_emb[(size_t)(m0 + r) * kE + k0 + c8 * 8]);
            *reinterpret_cast<uint4*>(&As[r][c8 * 8]) = v;
        }
        {
            int r = tid >> 2, c8 = tid & 3;
            const float* src = &W[(size_t)(n0 + r) * kE + k0 + c8 * 8];
            float4 v0 = *reinterpret_cast<const float4*>(src);
            float4 v1 = *reinterpret_cast<const float4*>(src + 4);
            __half2* dst = reinterpret_cast<__half2*>(&Bs[r][c8 * 8]);
            dst[0] = __floats2half2_rn(v0.x, v0.y);
            dst[1] = __floats2half2_rn(v0.z, v0.w);
            dst[2] = __floats2half2_rn(v1.x, v1.y);
            dst[3] = __floats2half2_rn(v1.z, v1.w);
        }
        __syncthreads();
#pragma unroll
        for (int kk = 0; kk < BK; kk += 16) {
            wmma::fragment<wmma::matrix_a, 16, 16, 16, __half,
                           wmma::row_major> a[2];
            wmma::fragment<wmma::matrix_b, 16, 16, 16, __half,
                           wmma::col_major> b[2];
            wmma::load_matrix_sync(a[0], &As[wm * 32][kk], BKP);
            wmma::load_matrix_sync(a[1], &As[wm * 32 + 16][kk], BKP);
            wmma::load_matrix_sync(b[0], &Bs[wn * 32][kk], BKP);
            wmma::load_matrix_sync(b[1], &Bs[wn * 32 + 16][kk], BKP);
#pragma unroll
            for (int i = 0; i < 2; i++)
#pragma unroll
                for (int j = 0; j < 2; j++)
                    wmma::mma_sync(acc[i][j], a[i], b[j], acc[i][j]);
        }
        __syncthreads();
    }
#pragma unroll
    for (int i = 0; i < 2; i++)
#pragma unroll
        for (int j = 0; j < 2; j++)
            wmma::store_matrix_sync(&Cs[wid][i * 16][j * 16], acc[i][j], 32,
                                    wmma::mem_row_major);
    __syncwarp();
    int gm = m0 + wm * 32, gn = n0 + wn * 32;
    float bv = bias[gn + lane];
#pragma unroll
    for (int r = 0; r < 32; r++) {
        int m = gm + r;                       // m = b*T + t
        int trow = (m & (kT - 1)) * kB + (m >> 9);  // -> t*B + b
        xp[(size_t)trow * k3H + gn + lane] =
            __float2half_rn(Cs[wid][r][lane] + bv);
    }
}

// ---------------------------------------------------------------------------
// Persistent GRU recurrence — EXACT R10 structure (best known), fp16 xp.
// 128 blocks (64/dir), 16 hidden cols each. 16 warps = 4 m-tiles x 4
// K-quarters; A fragments row-major m16n16k16 from global h; B from SMEM W.
constexpr int WS_ST = 1032;                   // halves: 1024 + 8 pad
constexpr int CS_ST = 52;
constexpr int SM_WS_H = 48 * WS_ST;           // 49536 halves = 99072 B
constexpr int SM_CBUF = kB * CS_ST;           // 3328 floats per buffer
constexpr size_t SM_BYTES =
    (size_t)SM_WS_H * 2 + (size_t)(2 * SM_CBUF + 64) * 4;  // ~126 KB
constexpr int NTHR = 512;                     // 16 warps

__global__ void __launch_bounds__(NTHR, 1)
step_persist_kernel(const float* __restrict__ Whf,
                    const float* __restrict__ Whb,
                    const float* __restrict__ bhf,
                    const float* __restrict__ bhb,
                    float* __restrict__ out) {
    extern __shared__ char smraw[];
    __half* Ws = reinterpret_cast<__half*>(smraw);      // [48][WS_ST] halves
    float* bufA = reinterpret_cast<float*>(smraw + SM_WS_H * 2);
    float* bufB = bufA + SM_CBUF;
    float* bsl = bufB + SM_CBUF;                        // [48]

    int bx = blockIdx.x;
    int dir = bx >> 6;
    int j0 = (bx & 63) * 16;
    const float* W = dir ? Whb : Whf;
    const float* bhh = dir ? bhb : bhf;
    const __half* xp = g_xp + (size_t)dir * kXPSZ;

    int tid = threadIdx.x, wid = tid >> 5;
    int ks = wid >> 2;     // K-quarter 0..3 (256 K each)
    int mt = wid & 3;      // m-tile 0..3

    // preload W slice (48 rows x 1024) into SMEM as fp16
    for (int i = tid; i < 48 * 256; i += NTHR) {
        int r = i >> 8, c4 = i & 255;  // 4 floats per chunk
        int wrow = (r >> 4) * kH + j0 + (r & 15);
        float4 v = *reinterpret_cast<const float4*>(
            &W[(size_t)wrow * kH + c4 * 4]);
        __half2* dst = reinterpret_cast<__half2*>(&Ws[r * WS_ST + c4 * 4]);
        dst[0] = __floats2half2_rn(v.x, v.y);
        dst[1] = __floats2half2_rn(v.z, v.w);
    }
    if (tid < 48) bsl[tid] = bhh[(tid >> 4) * kH + j0 + (tid & 15)];
    __syncthreads();

    for (int s = 0; s < kT; s++) {
        int parity = s & 1;
        const __half* hprev = g_h[parity][dir];   // [b][j] row-major
        __half* hnext = g_h[parity ^ 1][dir];
        int t_idx = dir ? (kT - 1 - s) : s;
        const __half* xpt = xp + (size_t)t_idx * kB * k3H;

        // preload epilogue operands (latency hides behind mainloop)
        float pxr[2], pxz[2], pxn[2], php[2];
#pragma unroll
        for (int k = 0; k < 2; k++) {
            int idx = tid + k * NTHR;  // < 1024 always
            int b = idx >> 4, jj = idx & 15, j = j0 + jj;
            const __half* xpr = xpt + (size_t)b * k3H;
            pxr[k] = __half2float(xpr[j]);
            pxz[k] = __half2float(xpr[kH + j]);
            pxn[k] = __half2float(xpr[2 * kH + j]);
            php[k] = __half2float(hprev[b * kH + j]);
        }

        // ---------------- mainloop: no block syncs, 2-deep A ring ---------
        wmma::fragment<wmma::accumulator, 16, 16, 16, float> acc[3];
#pragma unroll
        for (int g = 0; g < 3; g++) wmma::fill_fragment(acc[g], 0.0f);

        const __half* aBase = hprev + (size_t)(mt * 16) * kH + ks * 256;
        wmma::fragment<wmma::matrix_a, 16, 16, 16, __half, wmma::row_major>
            afr[2];
        wmma::load_matrix_sync(afr[0], aBase, kH);
#pragma unroll 4
        for (int f = 0; f < 16; f++) {   // 16 k16-fragments per K-quarter
            int cur = f & 1;
            if (f < 15)
                wmma::load_matrix_sync(afr[cur ^ 1], aBase + (f + 1) * 16, kH);
            int kcol = ks * 256 + f * 16;
#pragma unroll
            for (int g = 0; g < 3; g++) {
                wmma::fragment<wmma::matrix_b, 16, 16, 16, __half,
                               wmma::col_major> b;
                wmma::load_matrix_sync(b, &Ws[(g * 16) * WS_ST + kcol], WS_ST);
                wmma::mma_sync(acc[g], afr[cur], b, acc[g]);
            }
        }

        // ---------------- K-partial reduction (2 syncs) -------------------
        float* mybuf = (ks & 1) ? bufB : bufA;
        if (ks >= 2) {
#pragma unroll
            for (int g = 0; g < 3; g++)
                wmma::store_matrix_sync(&mybuf[(mt * 16) * CS_ST + g * 16],
                                        acc[g], CS_ST, wmma::mem_row_major);
        }
        __syncthreads();
        if (ks < 2) {
#pragma unroll
            for (int g = 0; g < 3; g++) {
                wmma::fragment<wmma::accumulator, 16, 16, 16, float> c;
                wmma::load_matrix_sync(c, &mybuf[(mt * 16) * CS_ST + g * 16],
                                       CS_ST, wmma::mem_row_major);
#pragma unroll
                for (int e = 0; e < c.num_elements; e++)
                    acc[g].x[e] += c.x[e];
                wmma::store_matrix_sync(&mybuf[(mt * 16) * CS_ST + g * 16],
                                        acc[g], CS_ST, wmma::mem_row_major);
            }
        }
        __syncthreads();

        // ---------------- gate fusion + h update + output (R10 order) -----
#pragma unroll
        for (int k = 0; k < 2; k++) {
            int idx = tid + k * NTHR;
            int b = idx >> 4, jj = idx & 15, j = j0 + jj;
            float ghr = bufA[b * CS_ST + jj] + bufB[b * CS_ST + jj] + bsl[jj];
            float ghz = bufA[b * CS_ST + 16 + jj] + bufB[b * CS_ST + 16 + jj] +
                        bsl[16 + jj];
            float ghn = bufA[b * CS_ST + 32 + jj] + bufB[b * CS_ST + 32 + jj] +
                        bsl[32 + jj];
            float r = 1.0f / (1.0f + __expf(-(pxr[k] + ghr)));
            float z = 1.0f / (1.0f + __expf(-(pxz[k] + ghz)));
            float n = tanhf(pxn[k] + r * ghn);
            float hv = (1.0f - z) * n + z * php[k];
            hnext[b * kH + j] = __float2half_rn(hv);
            out[(size_t)(b * kT + t_idx) * (2 * kH) + dir * kH + j] = hv;
        }

        // per-direction global barrier (R10 ordering: poll directly after)
        __threadfence();
        __syncthreads();
        if (tid == 0) {
            atomicAdd(&g_bar[dir], 1u);
            unsigned int target = 64u * (unsigned int)(s + 1);
            unsigned int v;
            do {
                asm volatile("ld.acquire.gpu.u32 %0, [%1];"
                             : "=r"(v) : "l"(&g_bar[dir]) : "memory");
            } while (v < target);
        }
        __syncthreads();
    }
}

// ---------------------------------------------------------------------------
__global__ void fc_kernel(const float* __restrict__ fcW,
                          const float* __restrict__ fcb,
                          float* __restrict__ out) {
    __shared__ float hc[2 * kH];
    int b = blockIdx.y;
    int tid = threadIdx.x, wid = tid >> 5, lane = tid & 31;
    for (int k = tid; k < 2 * kH; k += 256) {
        hc[k] = (k < kH) ? __half2float(g_h[0][0][b * kH + k])
                         : __half2float(g_h[0][1][b * kH + k - kH]);
    }
    __syncthreads();
    int o = blockIdx.x * 8 + wid;
    const float4* wr = reinterpret_cast<const float4*>(&fcW[(size_t)o * 2 * kH]);
    const float4* hr = reinterpret_cast<const float4*>(hc);
    float sum = 0.0f;
    for (int i = lane; i < (2 * kH) / 4; i += 32) {
        float4 w = wr[i], h = hr[i];
        sum += w.x * h.x + w.y * h.y + w.z * h.z + w.w * h.w;
    }
#pragma unroll
    for (int off = 16; off; off >>= 1)
        sum += __shfl_xor_sync(0xffffffff, sum, off);
    if (lane == 0) out[kOUTSZ + (size_t)b * kH + o] = tanhf(sum + fcb[o]);
}

// ---------------------------------------------------------------------------
extern "C" void kernel_launch(void* const* d_in, const int* in_sizes, int n_in,
                              void* d_out, int out_size) {
    const int* seqs      = (const int*)d_in[0];
    const float* embW    = (const float*)d_in[1];
    const float* W_ih_f  = (const float*)d_in[2];
    const float* W_hh_f  = (const float*)d_in[3];
    const float* b_ih_f  = (const float*)d_in[4];
    const float* b_hh_f  = (const float*)d_in[5];
    const float* W_ih_b  = (const float*)d_in[6];
    const float* W_hh_b  = (const float*)d_in[7];
    const float* b_ih_b  = (const float*)d_in[8];
    const float* b_hh_b  = (const float*)d_in[9];
    const float* fc_W    = (const float*)d_in[10];
    const float* fc_b    = (const float*)d_in[11];
    float* out = (float*)d_out;

    static bool attr_set = false;
    if (!attr_set) {
        cudaFuncSetAttribute(step_persist_kernel,
                             cudaFuncAttributeMaxDynamicSharedMemorySize,
                             (int)SM_BYTES);
        attr_set = true;
    }

    zero_h_kernel<<<512, 256>>>();
    gather_kernel<<<kBT, 128>>>(seqs, embW);
    xp_gemm_kernel<<<dim3(48, 256, 2), 256>>>(W_ih_f, W_ih_b, b_ih_f, b_ih_b);
    step_persist_kernel<<<128, NTHR, SM_BYTES>>>(W_hh_f, W_hh_b, b_hh_f,
                                                 b_hh_b, out);
    fc_kernel<<<dim3(kH / 8, kB), 256>>>(fc_W, fc_b, out);
}

// round 17
// speedup vs baseline: 1.5391x; 1.0298x over previous
#include <cuda_runtime.h>
#include <cstdint>
#include <cuda_fp16.h>
#include <mma.h>
using namespace nvcuda;

// Problem dims
constexpr int kB = 64;      // batch
constexpr int kT = 512;     // seq len
constexpr int kE = 512;     // embed
constexpr int kH = 1024;    // hidden
constexpr int kBT = kB * kT;           // 32768
constexpr int k3H = 3 * kH;            // 3072
constexpr size_t kXPSZ = (size_t)kBT * k3H;       // per-dir xp elements
constexpr size_t kOUTSZ = (size_t)kBT * 2 * kH;   // outputs elements

// Scratch
__device__ __half g_emb[(size_t)kBT * kE];  // 32 MB (fp16 embeddings)
__device__ __half g_xp[2 * kXPSZ];          // 403 MB, [dir][t][b][3H] fp16
__device__ __half g_h[2][2][kB * kH];       // [parity][dir][b][j] fp16
__device__ unsigned int g_bar[2];           // per-dir step barrier counters

// ---------------------------------------------------------------------------
__global__ void zero_h_kernel() {
    int idx = blockIdx.x * blockDim.x + threadIdx.x;  // 131072 uints = 512KB
    ((unsigned int*)g_h)[idx] = 0u;
    if (blockIdx.x == 0 && threadIdx.x < 2) g_bar[threadIdx.x] = 0u;
}

// emb[m, :] = half(embed_W[seqs[m], :])
__global__ void gather_kernel(const int* __restrict__ seqs,
                              const float* __restrict__ embW) {
    int m = blockIdx.x;
    int t = threadIdx.x;  // 128 threads, 4 elems each
    int row = seqs[m];
    float4 v = reinterpret_cast<const float4*>(embW)[(size_t)row * (kE / 4) + t];
    __half2 h0 = __floats2half2_rn(v.x, v.y);
    __half2 h1 = __floats2half2_rn(v.z, v.w);
    *reinterpret_cast<__half2*>(&g_emb[(size_t)m * kE + t * 4]) = h0;
    *reinterpret_cast<__half2*>(&g_emb[(size_t)m * kE + t * 4 + 2]) = h1;
}

// ---------------------------------------------------------------------------
// xp = emb @ W_ih^T + b_ih (fp16 in, fp32 accum, fp16 OUT), rows [t][b].
__global__ void xp_gemm_kernel(const float* __restrict__ Wf,
                               const float* __restrict__ Wb,
                               const float* __restrict__ bf,
                               const float* __restrict__ bb) {
    constexpr int BM = 128, BN = 64, BK = 32, BKP = 40;
    __shared__ __half As[BM][BKP];
    __shared__ __half Bs[BN][BKP];
    __shared__ float Cs[8][32][32];

    int dir = blockIdx.z;
    const float* W = dir ? Wb : Wf;
    const float* bias = dir ? bb : bf;
    __half* xp = g_xp + (size_t)dir * kXPSZ;

    int m0 = blockIdx.y * BM, n0 = blockIdx.x * BN;
    int tid = threadIdx.x, wid = tid >> 5, lane = tid & 31;
    int wm = wid >> 1, wn = wid & 1;

    wmma::fragment<wmma::accumulator, 16, 16, 16, float> acc[2][2];
#pragma unroll
    for (int i = 0; i < 2; i++)
#pragma unroll
        for (int j = 0; j < 2; j++) wmma::fill_fragment(acc[i][j], 0.0f);

    for (int k0 = 0; k0 < kE; k0 += BK) {
#pragma unroll
        for (int it = 0; it < 2; it++) {
            int i = tid + it * 256;
            int r = i >> 2, c8 = i & 3;
            uint4 v = *reinterpret_cast<const uint4*>(
                &g_emb[(size_t)(m0 + r) * kE + k0 + c8 * 8]);
            *reinterpret_cast<uint4*>(&As[r][c8 * 8]) = v;
        }
        {
            int r = tid >> 2, c8 = tid & 3;
            const float* src = &W[(size_t)(n0 + r) * kE + k0 + c8 * 8];
            float4 v0 = *reinterpret_cast<const float4*>(src);
            float4 v1 = *reinterpret_cast<const float4*>(src + 4);
            __half2* dst = reinterpret_cast<__half2*>(&Bs[r][c8 * 8]);
            dst[0] = __floats2half2_rn(v0.x, v0.y);
            dst[1] = __floats2half2_rn(v0.z, v0.w);
            dst[2] = __floats2half2_rn(v1.x, v1.y);
            dst[3] = __floats2half2_rn(v1.z, v1.w);
        }
        __syncthreads();
#pragma unroll
        for (int kk = 0; kk < BK; kk += 16) {
            wmma::fragment<wmma::matrix_a, 16, 16, 16, __half,
                           wmma::row_major> a[2];
            wmma::fragment<wmma::matrix_b, 16, 16, 16, __half,
                           wmma::col_major> b[2];
            wmma::load_matrix_sync(a[0], &As[wm * 32][kk], BKP);
            wmma::load_matrix_sync(a[1], &As[wm * 32 + 16][kk], BKP);
            wmma::load_matrix_sync(b[0], &Bs[wn * 32][kk], BKP);
            wmma::load_matrix_sync(b[1], &Bs[wn * 32 + 16][kk], BKP);
#pragma unroll
            for (int i = 0; i < 2; i++)
#pragma unroll
                for (int j = 0; j < 2; j++)
                    wmma::mma_sync(acc[i][j], a[i], b[j], acc[i][j]);
        }
        __syncthreads();
    }
#pragma unroll
    for (int i = 0; i < 2; i++)
#pragma unroll
        for (int j = 0; j < 2; j++)
            wmma::store_matrix_sync(&Cs[wid][i * 16][j * 16], acc[i][j], 32,
                                    wmma::mem_row_major);
    __syncwarp();
    int gm = m0 + wm * 32, gn = n0 + wn * 32;
    float bv = bias[gn + lane];
#pragma unroll
    for (int r = 0; r < 32; r++) {
        int m = gm + r;                       // m = b*T + t
        int trow = (m & (kT - 1)) * kB + (m >> 9);  // -> t*B + b
        xp[(size_t)trow * k3H + gn + lane] =
            __float2half_rn(Cs[wid][r][lane] + bv);
    }
}

// ---------------------------------------------------------------------------
// Persistent GRU recurrence — R16 structure; barrier publish via single
// release-reduction (no per-thread __threadfence).
constexpr int WS_ST = 1032;                   // halves: 1024 + 8 pad
constexpr int CS_ST = 52;
constexpr int SM_WS_H = 48 * WS_ST;           // 49536 halves = 99072 B
constexpr int SM_CBUF = kB * CS_ST;           // 3328 floats per buffer
constexpr size_t SM_BYTES =
    (size_t)SM_WS_H * 2 + (size_t)(2 * SM_CBUF + 64) * 4;  // ~126 KB
constexpr int NTHR = 512;                     // 16 warps

__global__ void __launch_bounds__(NTHR, 1)
step_persist_kernel(const float* __restrict__ Whf,
                    const float* __restrict__ Whb,
                    const float* __restrict__ bhf,
                    const float* __restrict__ bhb,
                    float* __restrict__ out) {
    extern __shared__ char smraw[];
    __half* Ws = reinterpret_cast<__half*>(smraw);      // [48][WS_ST] halves
    float* bufA = reinterpret_cast<float*>(smraw + SM_WS_H * 2);
    float* bufB = bufA + SM_CBUF;
    float* bsl = bufB + SM_CBUF;                        // [48]

    int bx = blockIdx.x;
    int dir = bx >> 6;
    int j0 = (bx & 63) * 16;
    const float* W = dir ? Whb : Whf;
    const float* bhh = dir ? bhb : bhf;
    const __half* xp = g_xp + (size_t)dir * kXPSZ;

    int tid = threadIdx.x, wid = tid >> 5;
    int ks = wid >> 2;     // K-quarter 0..3 (256 K each)
    int mt = wid & 3;      // m-tile 0..3

    // preload W slice (48 rows x 1024) into SMEM as fp16
    for (int i = tid; i < 48 * 256; i += NTHR) {
        int r = i >> 8, c4 = i & 255;  // 4 floats per chunk
        int wrow = (r >> 4) * kH + j0 + (r & 15);
        float4 v = *reinterpret_cast<const float4*>(
            &W[(size_t)wrow * kH + c4 * 4]);
        __half2* dst = reinterpret_cast<__half2*>(&Ws[r * WS_ST + c4 * 4]);
        dst[0] = __floats2half2_rn(v.x, v.y);
        dst[1] = __floats2half2_rn(v.z, v.w);
    }
    if (tid < 48) bsl[tid] = bhh[(tid >> 4) * kH + j0 + (tid & 15)];
    __syncthreads();

    for (int s = 0; s < kT; s++) {
        int parity = s & 1;
        const __half* hprev = g_h[parity][dir];   // [b][j] row-major
        __half* hnext = g_h[parity ^ 1][dir];
        int t_idx = dir ? (kT - 1 - s) : s;
        const __half* xpt = xp + (size_t)t_idx * kB * k3H;

        // preload epilogue operands (latency hides behind mainloop)
        float pxr[2], pxz[2], pxn[2], php[2];
#pragma unroll
        for (int k = 0; k < 2; k++) {
            int idx = tid + k * NTHR;  // < 1024 always
            int b = idx >> 4, jj = idx & 15, j = j0 + jj;
            const __half* xpr = xpt + (size_t)b * k3H;
            pxr[k] = __half2float(xpr[j]);
            pxz[k] = __half2float(xpr[kH + j]);
            pxn[k] = __half2float(xpr[2 * kH + j]);
            php[k] = __half2float(hprev[b * kH + j]);
        }

        // ---------------- mainloop: no block syncs, 2-deep A ring ---------
        wmma::fragment<wmma::accumulator, 16, 16, 16, float> acc[3];
#pragma unroll
        for (int g = 0; g < 3; g++) wmma::fill_fragment(acc[g], 0.0f);

        const __half* aBase = hprev + (size_t)(mt * 16) * kH + ks * 256;
        wmma::fragment<wmma::matrix_a, 16, 16, 16, __half, wmma::row_major>
            afr[2];
        wmma::load_matrix_sync(afr[0], aBase, kH);
#pragma unroll 4
        for (int f = 0; f < 16; f++) {   // 16 k16-fragments per K-quarter
            int cur = f & 1;
            if (f < 15)
                wmma::load_matrix_sync(afr[cur ^ 1], aBase + (f + 1) * 16, kH);
            int kcol = ks * 256 + f * 16;
#pragma unroll
            for (int g = 0; g < 3; g++) {
                wmma::fragment<wmma::matrix_b, 16, 16, 16, __half,
                               wmma::col_major> b;
                wmma::load_matrix_sync(b, &Ws[(g * 16) * WS_ST + kcol], WS_ST);
                wmma::mma_sync(acc[g], afr[cur], b, acc[g]);
            }
        }

        // ---------------- K-partial reduction (2 syncs) -------------------
        float* mybuf = (ks & 1) ? bufB : bufA;
        if (ks >= 2) {
#pragma unroll
            for (int g = 0; g < 3; g++)
                wmma::store_matrix_sync(&mybuf[(mt * 16) * CS_ST + g * 16],
                                        acc[g], CS_ST, wmma::mem_row_major);
        }
        __syncthreads();
        if (ks < 2) {
#pragma unroll
            for (int g = 0; g < 3; g++) {
                wmma::fragment<wmma::accumulator, 16, 16, 16, float> c;
                wmma::load_matrix_sync(c, &mybuf[(mt * 16) * CS_ST + g * 16],
                                       CS_ST, wmma::mem_row_major);
#pragma unroll
                for (int e = 0; e < c.num_elements; e++)
                    acc[g].x[e] += c.x[e];
                wmma::store_matrix_sync(&mybuf[(mt * 16) * CS_ST + g * 16],
                                        acc[g], CS_ST, wmma::mem_row_major);
            }
        }
        __syncthreads();

        // ---------------- gate fusion + h update + output (R10 order) -----
#pragma unroll
        for (int k = 0; k < 2; k++) {
            int idx = tid + k * NTHR;
            int b = idx >> 4, jj = idx & 15, j = j0 + jj;
            float ghr = bufA[b * CS_ST + jj] + bufB[b * CS_ST + jj] + bsl[jj];
            float ghz = bufA[b * CS_ST + 16 + jj] + bufB[b * CS_ST + 16 + jj] +
                        bsl[16 + jj];
            float ghn = bufA[b * CS_ST + 32 + jj] + bufB[b * CS_ST + 32 + jj] +
                        bsl[32 + jj];
            float r = 1.0f / (1.0f + __expf(-(pxr[k] + ghr)));
            float z = 1.0f / (1.0f + __expf(-(pxz[k] + ghz)));
            float n = tanhf(pxn[k] + r * ghn);
            float hv = (1.0f - z) * n + z * php[k];
            hnext[b * kH + j] = __float2half_rn(hv);
            out[(size_t)(b * kT + t_idx) * (2 * kH) + dir * kH + j] = hv;
        }

        // per-direction global barrier: single release-reduction publishes
        // all block stores (cumulativity via __syncthreads); no threadfence.
        __syncthreads();
        if (tid == 0) {
            asm volatile("red.release.gpu.global.add.u32 [%0], %1;" ::"l"(
                             &g_bar[dir]),
                         "r"(1u)
                         : "memory");
            unsigned int target = 64u * (unsigned int)(s + 1);
            unsigned int v;
            do {
                asm volatile("ld.acquire.gpu.u32 %0, [%1];"
                             : "=r"(v) : "l"(&g_bar[dir]) : "memory");
            } while (v < target);
        }
        __syncthreads();
    }
}

// ---------------------------------------------------------------------------
__global__ void fc_kernel(const float* __restrict__ fcW,
                          const float* __restrict__ fcb,
                          float* __restrict__ out) {
    __shared__ float hc[2 * kH];
    int b = blockIdx.y;
    int tid = threadIdx.x, wid = tid >> 5, lane = tid & 31;
    for (int k = tid; k < 2 * kH; k += 256) {
        hc[k] = (k < kH) ? __half2float(g_h[0][0][b * kH + k])
                         : __half2float(g_h[0][1][b * kH + k - kH]);
    }
    __syncthreads();
    int o = blockIdx.x * 8 + wid;
    const float4* wr = reinterpret_cast<const float4*>(&fcW[(size_t)o * 2 * kH]);
    const float4* hr = reinterpret_cast<const float4*>(hc);
    float sum = 0.0f;
    for (int i = lane; i < (2 * kH) / 4; i += 32) {
        float4 w = wr[i], h = hr[i];
        sum += w.x * h.x + w.y * h.y + w.z * h.z + w.w * h.w;
    }
#pragma unroll
    for (int off = 16; off; off >>= 1)
        sum += __shfl_xor_sync(0xffffffff, sum, off);
    if (lane == 0) out[kOUTSZ + (size_t)b * kH + o] = tanhf(sum + fcb[o]);
}

// ---------------------------------------------------------------------------
extern "C" void kernel_launch(void* const* d_in, const int* in_sizes, int n_in,
                              void* d_out, int out_size) {
    const int* seqs      = (const int*)d_in[0];
    const float* embW    = (const float*)d_in[1];
    const float* W_ih_f  = (const float*)d_in[2];
    const float* W_hh_f  = (const float*)d_in[3];
    const float* b_ih_f  = (const float*)d_in[4];
    const float* b_hh_f  = (const float*)d_in[5];
    const float* W_ih_b  = (const float*)d_in[6];
    const float* W_hh_b  = (const float*)d_in[7];
    const float* b_ih_b  = (const float*)d_in[8];
    const float* b_hh_b  = (const float*)d_in[9];
    const float* fc_W    = (const float*)d_in[10];
    const float* fc_b    = (const float*)d_in[11];
    float* out = (float*)d_out;

    static bool attr_set = false;
    if (!attr_set) {
        cudaFuncSetAttribute(step_persist_kernel,
                             cudaFuncAttributeMaxDynamicSharedMemorySize,
                             (int)SM_BYTES);
        attr_set = true;
    }

    zero_h_kernel<<<512, 256>>>();
    gather_kernel<<<kBT, 128>>>(seqs, embW);
    xp_gemm_kernel<<<dim3(48, 256, 2), 256>>>(W_ih_f, W_ih_b, b_ih_f, b_ih_b);
    step_persist_kernel<<<128, NTHR, SM_BYTES>>>(W_hh_f, W_hh_b, b_hh_f,
                                                 b_hh_b, out);
    fc_kernel<<<dim3(kH / 8, kB), 256>>>(fc_W, fc_b, out);
}